// round 1
// baseline (speedup 1.0000x reference)
#include <cuda_runtime.h>
#include <math.h>

#define BATCH 512
#define FEAT  512
#define NSPLIT 255
#define NNODE  511
#define NC     21

// Scratch (no allocation allowed)
__device__ float d_qsplit[BATCH * NSPLIT];
__device__ float d_qnode[BATCH * NNODE];   // [b][n]
__device__ float d_ga[NNODE * NC];
__device__ float d_anode[NNODE];

// ---------------------------------------------------------------------------
// K1: q_split = x @ W + b   (512x512 @ 512x255)
// Block: 256 threads, 4 batch rows; thread s = output split column.
// ---------------------------------------------------------------------------
__global__ void k_gemm(const float* __restrict__ x,
                       const float* __restrict__ W,
                       const float* __restrict__ bias) {
    __shared__ float xs[4][FEAT];
    const int tid = threadIdx.x;
    const int b0 = blockIdx.x * 4;

    // coalesced load of 4 contiguous x rows
    for (int i = tid; i < 4 * FEAT; i += 256) {
        xs[i >> 9][i & 511] = x[b0 * FEAT + i];
    }
    __syncthreads();

    const int s = tid;
    if (s < NSPLIT) {
        float a0 = 0.f, a1 = 0.f, a2 = 0.f, a3 = 0.f;
        #pragma unroll 4
        for (int f = 0; f < FEAT; f += 4) {
            float w0 = W[(f + 0) * NSPLIT + s];
            float w1 = W[(f + 1) * NSPLIT + s];
            float w2 = W[(f + 2) * NSPLIT + s];
            float w3 = W[(f + 3) * NSPLIT + s];
            float4 v0 = *(const float4*)&xs[0][f];
            float4 v1 = *(const float4*)&xs[1][f];
            float4 v2 = *(const float4*)&xs[2][f];
            float4 v3 = *(const float4*)&xs[3][f];
            a0 += v0.x * w0 + v0.y * w1 + v0.z * w2 + v0.w * w3;
            a1 += v1.x * w0 + v1.y * w1 + v1.z * w2 + v1.w * w3;
            a2 += v2.x * w0 + v2.y * w1 + v2.z * w2 + v2.w * w3;
            a3 += v3.x * w0 + v3.y * w1 + v3.z * w2 + v3.w * w3;
        }
        const float bb = bias[s];
        d_qsplit[(b0 + 0) * NSPLIT + s] = a0 + bb;
        d_qsplit[(b0 + 1) * NSPLIT + s] = a1 + bb;
        d_qsplit[(b0 + 2) * NSPLIT + s] = a2 + bb;
        d_qsplit[(b0 + 3) * NSPLIT + s] = a3 + bb;
    }
}

// ---------------------------------------------------------------------------
// K2: q_node[b][n] = min(1, min over ancestors s of sign * q_split[b][s])
// Block per batch row b; thread per node n.
// ---------------------------------------------------------------------------
__global__ void k_qnode() {
    __shared__ float sq[NSPLIT];
    const int b = blockIdx.x;
    const int tid = threadIdx.x;
    if (tid < NSPLIT) sq[tid] = d_qsplit[b * NSPLIT + tid];
    __syncthreads();
    if (tid < NNODE) {
        float m = 1.0f;
        int a = tid;
        while (a > 0) {
            int p = (a - 1) >> 1;
            float q = sq[p];
            m = fminf(m, (a == 2 * p + 1) ? -q : q);
            a = p;
        }
        d_qnode[b * NNODE + tid] = m;
    }
}

// ---------------------------------------------------------------------------
// K3: g_a[n][c] = 0.5*a_c^2 + 0.5 * sum_b [a_c <= q+0.5] * (a_c - (q+0.5))^2
// Block per node n; thread per batch element.
// ---------------------------------------------------------------------------
__global__ void k_ga() {
    const int n = blockIdx.x;
    const int tid = threadIdx.x;   // == b
    const float v = d_qnode[tid * NNODE + n];
    const float qn5 = v + 0.5f;

    float acc[NC];
    #pragma unroll
    for (int c = 0; c < NC; c++) {
        float ac = c * 0.05f;
        float d = ac - qn5;
        acc[c] = (ac <= qn5) ? d * d : 0.0f;
    }
    // warp-level tree sum for each candidate
    #pragma unroll
    for (int c = 0; c < NC; c++) {
        #pragma unroll
        for (int off = 16; off; off >>= 1)
            acc[c] += __shfl_xor_sync(0xffffffffu, acc[c], off);
    }
    __shared__ float part[16][NC];
    const int w = tid >> 5, l = tid & 31;
    if (l == 0) {
        #pragma unroll
        for (int c = 0; c < NC; c++) part[w][c] = acc[c];
    }
    __syncthreads();
    if (tid < NC) {
        float s = 0.f;
        #pragma unroll
        for (int ww = 0; ww < 16; ww++) s += part[ww][tid];
        float ac = tid * 0.05f;
        d_ga[n * NC + tid] = 0.5f * ac * ac + 0.5f * s;
    }
}

// ---------------------------------------------------------------------------
// K4: sequential isotonic merge scan. Single block, 512 threads.
// n2g row i == (1-k_i) e_i + k_i e_par(i)  (k_i = merge count, parent fixed).
// Early exit: cond==false is a fixed point of the reference scan.
// ---------------------------------------------------------------------------
__global__ void k_scan() {
    __shared__ float s_ag[NNODE];
    __shared__ float s_an[NNODE];
    __shared__ int   s_k[NNODE];
    __shared__ float s_rv[16];
    __shared__ int   s_ri[16];
    __shared__ int   s_t;
    __shared__ int   s_cond;

    const int tid = threadIdx.x;

    // init: k = 0, a_grp[g] = softmin-weighted candidate for singleton group g
    if (tid < NNODE) {
        s_k[tid] = 0;
        float xv[NC];
        float m = -1e30f;
        #pragma unroll
        for (int c = 0; c < NC; c++) {
            float g = d_ga[tid * NC + c];
            xv[c] = -100.0f * g;
            m = fmaxf(m, xv[c]);
        }
        float num = 0.f, den = 0.f;
        #pragma unroll
        for (int c = 0; c < NC; c++) {
            float e = expf(xv[c] - m);
            num += (c * 0.05f) * e;
            den += e;
        }
        s_ag[tid] = num / den;
    }
    __syncthreads();

    for (int it = 0; it < NNODE + 1; it++) {
        // 1. a_node and viol from current (k, a_grp)
        float viol = -1e30f;
        if (tid < NNODE) {
            int i = tid;
            float ai;
            if (i == 0) {
                ai = s_ag[0];
            } else {
                int pi = (i - 1) >> 1;
                float ki = (float)s_k[i];
                ai = (1.0f - ki) * s_ag[i] + ki * s_ag[pi];
            }
            s_an[i] = ai;
            float ap;
            if (i == 0) {
                ap = 1.0f;
            } else {
                int pi = (i - 1) >> 1;
                if (pi == 0) {
                    ap = s_ag[0];
                } else {
                    int gp = (pi - 1) >> 1;
                    float kp = (float)s_k[pi];
                    ap = (1.0f - kp) * s_ag[pi] + kp * s_ag[gp];
                }
            }
            viol = ai - ap;
        }

        // 2. block argmax with first-index tie-break (matches jnp.argmax)
        int idx = tid;
        #pragma unroll
        for (int off = 16; off; off >>= 1) {
            float vo = __shfl_xor_sync(0xffffffffu, viol, off);
            int   io = __shfl_xor_sync(0xffffffffu, idx, off);
            if (vo > viol || (vo == viol && io < idx)) { viol = vo; idx = io; }
        }
        if ((tid & 31) == 0) { s_rv[tid >> 5] = viol; s_ri[tid >> 5] = idx; }
        __syncthreads();

        if (tid == 0) {
            float bv = s_rv[0]; int bi = s_ri[0];
            #pragma unroll
            for (int w = 1; w < 16; w++) {
                float vo = s_rv[w]; int io = s_ri[w];
                if (vo > bv || (vo == bv && io < bi)) { bv = vo; bi = io; }
            }
            int cond = (bv <= 1e-8f) && (bi > 0);
            s_t = bi;
            s_cond = cond;
            if (cond) s_k[bi] += 1;   // merge: node bi moves one step toward parent
        }
        __syncthreads();

        if (!s_cond) break;   // fixed point -> remaining iterations are no-ops

        // 3. recompute a_grp for the two changed groups: parent(t) (warp0), t (warp1)
        const int t = s_t;
        const int wid = tid >> 5, lane = tid & 31;
        if (wid < 2) {
            int g = wid ? t : ((t - 1) >> 1);
            float xval = -1e30f;
            if (lane < NC) {
                float kg = (float)s_k[g];
                float gg = (1.0f - kg) * d_ga[g * NC + lane];
                int l = 2 * g + 1;
                if (l < NNODE)     gg += (float)s_k[l]     * d_ga[l * NC + lane];
                if (l + 1 < NNODE) gg += (float)s_k[l + 1] * d_ga[(l + 1) * NC + lane];
                xval = -100.0f * gg;
            }
            float m = xval;
            #pragma unroll
            for (int off = 16; off; off >>= 1)
                m = fmaxf(m, __shfl_xor_sync(0xffffffffu, m, off));
            float e = (lane < NC) ? expf(xval - m) : 0.0f;
            float num = (lane * 0.05f) * e;
            float den = e;
            #pragma unroll
            for (int off = 16; off; off >>= 1) {
                num += __shfl_xor_sync(0xffffffffu, num, off);
                den += __shfl_xor_sync(0xffffffffu, den, off);
            }
            if (lane == 0) s_ag[g] = num / den;
        }
        __syncthreads();
    }

    if (tid < NNODE) d_anode[tid] = s_an[tid];
}

// ---------------------------------------------------------------------------
// K5: trajectory = clip(q_node, 0, a_node)
// ---------------------------------------------------------------------------
__global__ void k_out(float* __restrict__ out) {
    int idx = blockIdx.x * blockDim.x + threadIdx.x;
    if (idx < BATCH * NNODE) {
        int n = idx % NNODE;
        float q = d_qnode[idx];
        float a = d_anode[n];
        out[idx] = fminf(fmaxf(q, 0.0f), a);
    }
}

extern "C" void kernel_launch(void* const* d_in, const int* in_sizes, int n_in,
                              void* d_out, int out_size) {
    const float* x = (const float*)d_in[0];
    const float* W = (const float*)d_in[1];
    const float* b = (const float*)d_in[2];
    // d_in[3] = max_depth (fixed at 8 for this problem's shapes)

    k_gemm<<<BATCH / 4, 256>>>(x, W, b);
    k_qnode<<<BATCH, 512>>>();
    k_ga<<<NNODE, 512>>>();
    k_scan<<<1, 512>>>();
    const int total = BATCH * NNODE;
    k_out<<<(total + 255) / 256, 256>>>((float*)d_out);
}

// round 5
// speedup vs baseline: 1.2369x; 1.2369x over previous
#include <cuda_runtime.h>
#include <math.h>

#define BATCH 512
#define FEAT  512
#define NSPLIT 255
#define NNODE  511
#define NC     21
#define NBLK   128
#define NTHR   512

typedef unsigned long long ull;

// ---- persistent scratch (no allocation allowed) ----
__device__ float d_part[2][BATCH][NSPLIT];   // per-feature-half partial GEMM
__device__ float d_qnode[BATCH * NNODE];     // [b][n]
__device__ float d_qnodeT[NNODE * BATCH];    // [n][b]
__device__ float d_ga[NNODE * NC];
__device__ float d_anode[NNODE];
__device__ unsigned g_ctr[8];                // zero-init; restored to 0 after each use
__device__ unsigned g_rel[8];                // monotonic release generations

// Software grid barrier: safe because all NBLK blocks are co-resident
// (128 blocks, 1 block/SM max smem usage, 148 SMs).
__device__ __forceinline__ void grid_bar(int i) {
    __threadfence();
    __syncthreads();
    if (threadIdx.x == 0) {
        volatile unsigned* rel = &g_rel[i];
        unsigned gen = *rel;            // release can't advance until we arrive
        __threadfence();
        unsigned old = atomicAdd(&g_ctr[i], 1u);
        if (old == NBLK - 1) {
            atomicExch(&g_ctr[i], 0u);  // reset for next launch/replay
            __threadfence();
            atomicAdd(&g_rel[i], 1u);   // release
        } else {
            while (*rel == gen) { __nanosleep(64); }
        }
    }
    __syncthreads();
}

// Monotone packing: larger viol wins; ties -> smaller index wins.
__device__ __forceinline__ ull packkey(float v, int idx) {
    unsigned u = __float_as_uint(v);
    u = (u & 0x80000000u) ? ~u : (u | 0x80000000u);
    return (((ull)u) << 32) | (unsigned)(0xFFFF - idx);
}

__global__ __launch_bounds__(NTHR, 1)
void k_fused(const float* __restrict__ x, const float* __restrict__ W,
             const float* __restrict__ bias, float* __restrict__ out) {
    __shared__ union {
        float xs[8][256];                 // phase 1: x tile
        float comb[256][8];               // phase 1: cross-half combine
        float sq[4][256];                 // phase 2: q_split rows
        float red[4][4][NC];              // phase 3: warp partials
        float an[512];                    // phase 5: a_node
        struct {                          // phase 4 (47,140 B)
            float ga[NNODE * NC];
            float ag[NNODE];
            int   kk[NNODE];
            ull   part[16];
        } scan;
    } sm;

    const int tid = threadIdx.x;
    const int bb  = blockIdx.x;

    // ===================== Phase 1: GEMM partials =====================
    // Block (rb, h): 8 batch rows, feature half h (256 feats).
    // Thread (s = tid&255, fh = tid>>8): split h's 256 feats into 2x128.
    {
        const int rb = bb >> 1, h = bb & 1;
        const int b0 = rb * 8;
        const int f0 = h * 256;
        for (int i = tid; i < 8 * 256; i += NTHR) {
            int r = i >> 8, c = i & 255;
            sm.xs[r][c] = x[(b0 + r) * FEAT + f0 + c];
        }
        __syncthreads();

        const int s  = tid & 255;
        const int fh = tid >> 8;
        float acc[8] = {0.f,0.f,0.f,0.f,0.f,0.f,0.f,0.f};
        if (s < NSPLIT) {
            const int fb = f0 + fh * 128;
            #pragma unroll 4
            for (int f = 0; f < 128; f++) {
                float wv = W[(fb + f) * NSPLIT + s];
                #pragma unroll
                for (int r = 0; r < 8; r++)
                    acc[r] += sm.xs[r][fh * 128 + f] * wv;
            }
        }
        __syncthreads();
        if (fh == 1 && s < NSPLIT) {
            #pragma unroll
            for (int r = 0; r < 8; r++) sm.comb[s][r] = acc[r];
        }
        __syncthreads();
        if (fh == 0 && s < NSPLIT) {
            #pragma unroll
            for (int r = 0; r < 8; r++)
                d_part[h][b0 + r][s] = acc[r] + sm.comb[s][r];
        }
    }
    grid_bar(0);

    // ===================== Phase 2: q_node (tree min) =====================
    {
        const int b0 = bb * 4;
        for (int i = tid; i < 4 * 256; i += NTHR) {
            int r = i >> 8, scol = i & 255;
            if (scol < NSPLIT)
                sm.sq[r][scol] = d_part[0][b0 + r][scol] + d_part[1][b0 + r][scol] + bias[scol];
        }
        __syncthreads();
        for (int i = tid; i < 4 * 512; i += NTHR) {
            int r = i >> 9, n = i & 511;
            if (n < NNODE) {
                float m = 1.0f;
                int a = n;
                while (a > 0) {
                    int p = (a - 1) >> 1;
                    float q = sm.sq[r][p];
                    m = fminf(m, (a == 2 * p + 1) ? -q : q);
                    a = p;
                }
                int b = b0 + r;
                d_qnode[b * NNODE + n] = m;
                d_qnodeT[n * BATCH + b] = m;
            }
        }
    }
    grid_bar(1);

    // ===================== Phase 3: g_a table =====================
    // Block bb handles nodes bb*4 .. bb*4+3; 128 threads per node.
    {
        const int sub = tid >> 7;
        const int n = bb * 4 + sub;
        const int bl = tid & 127;
        float acc[NC];
        #pragma unroll
        for (int c = 0; c < NC; c++) acc[c] = 0.f;
        if (n < NNODE) {
            #pragma unroll
            for (int j = 0; j < 4; j++) {
                float v = d_qnodeT[n * BATCH + bl + j * 128];
                float qn5 = v + 0.5f;
                #pragma unroll
                for (int c = 0; c < NC; c++) {
                    float ac = c * 0.05f;
                    float d = ac - qn5;
                    acc[c] += (ac <= qn5) ? d * d : 0.0f;
                }
            }
        }
        #pragma unroll
        for (int c = 0; c < NC; c++) {
            #pragma unroll
            for (int off = 16; off; off >>= 1)
                acc[c] += __shfl_xor_sync(0xffffffffu, acc[c], off);
        }
        if ((tid & 31) == 0) {
            #pragma unroll
            for (int c = 0; c < NC; c++) sm.red[sub][(tid >> 5) & 3][c] = acc[c];
        }
        __syncthreads();
        if (bl < NC && n < NNODE) {
            int c = bl;
            float s = sm.red[sub][0][c] + sm.red[sub][1][c] + sm.red[sub][2][c] + sm.red[sub][3][c];
            float ac = c * 0.05f;
            d_ga[n * NC + c] = 0.5f * ac * ac + 0.5f * s;
        }
    }
    grid_bar(2);

    // ===================== Phase 4: isotonic merge scan (block 0 only) ===
    if (bb == 0) {
        float ai_last = 0.0f;
        for (int i = tid; i < NNODE * NC; i += NTHR)
            sm.scan.ga[i] = d_ga[i];
        __syncthreads();
        if (tid < NNODE) {
            sm.scan.kk[tid] = 0;
            const float* gn = &sm.scan.ga[tid * NC];
            float xv[NC]; float m = -1e30f;
            #pragma unroll
            for (int c = 0; c < NC; c++) { xv[c] = -100.0f * gn[c]; m = fmaxf(m, xv[c]); }
            float num = 0.f, den = 0.f;
            #pragma unroll
            for (int c = 0; c < NC; c++) { float e = expf(xv[c] - m); num += (c * 0.05f) * e; den += e; }
            sm.scan.ag[tid] = num / den;
        }
        __syncthreads();

        const ull THRESH = packkey(1e-8f, 0);
        const int wid = tid >> 5, lane = tid & 31;

        for (int it = 0; it < NNODE + 1; it++) {
            // a_node + violation from (k, a_grp)
            float viol = -1e30f;
            if (tid < NNODE) {
                float ai, ap;
                if (tid == 0) { ai = sm.scan.ag[0]; ap = 1.0f; }
                else {
                    int pi = (tid - 1) >> 1;
                    float ki = (float)sm.scan.kk[tid];
                    ai = (1.0f - ki) * sm.scan.ag[tid] + ki * sm.scan.ag[pi];
                    if (pi == 0) ap = sm.scan.ag[0];
                    else {
                        int gp = (pi - 1) >> 1;
                        float kp = (float)sm.scan.kk[pi];
                        ap = (1.0f - kp) * sm.scan.ag[pi] + kp * sm.scan.ag[gp];
                    }
                }
                ai_last = ai;
                viol = ai - ap;
            }
            // block argmax via packed 64-bit keys
            ull key = packkey(viol, tid);
            #pragma unroll
            for (int off = 16; off; off >>= 1) {
                ull o = __shfl_xor_sync(0xffffffffu, key, off);
                if (o > key) key = o;
            }
            if (lane == 0) sm.scan.part[wid] = key;
            __syncthreads();
            ull best = sm.scan.part[0];
            #pragma unroll
            for (int w = 1; w < 16; w++) { ull o = sm.scan.part[w]; if (o > best) best = o; }
            int t = 0xFFFF - (int)(best & 0xFFFFull);
            if (best > THRESH || t == 0) break;   // uniform: fixed point

            // recompute a_grp for groups parent(t) (warp0) and t (warp1)
            int p = (t - 1) >> 1;
            float newag = 0.f;
            int g = -1, kt_old = 0;
            if (wid < 2) {
                g = wid ? t : p;
                int l = 2 * g + 1;
                int kg_i = sm.scan.kk[g];
                if (wid == 1) kt_old = kg_i;
                float kg = (float)kg_i + (g == t ? 1.0f : 0.0f);
                float kl = (l < NNODE) ? ((float)sm.scan.kk[l] + (l == t ? 1.0f : 0.0f)) : 0.0f;
                float kr = (l + 1 < NNODE) ? ((float)sm.scan.kk[l + 1] + (l + 1 == t ? 1.0f : 0.0f)) : 0.0f;
                float xval = -1e30f;
                if (lane < NC) {
                    float gg = (1.0f - kg) * sm.scan.ga[g * NC + lane];
                    if (l < NNODE)     gg += kl * sm.scan.ga[l * NC + lane];
                    if (l + 1 < NNODE) gg += kr * sm.scan.ga[(l + 1) * NC + lane];
                    xval = -100.0f * gg;
                }
                float m = xval;
                #pragma unroll
                for (int off = 16; off; off >>= 1)
                    m = fmaxf(m, __shfl_xor_sync(0xffffffffu, m, off));
                float e = (lane < NC) ? expf(xval - m) : 0.0f;
                float num = (lane * 0.05f) * e;
                float den = e;
                #pragma unroll
                for (int off = 16; off; off >>= 1) {
                    num += __shfl_xor_sync(0xffffffffu, num, off);
                    den += __shfl_xor_sync(0xffffffffu, den, off);
                }
                newag = num / den;
            }
            __syncthreads();   // kk reads complete before kk[t] write
            if (wid < 2 && lane == 0) sm.scan.ag[g] = newag;
            if (wid == 1 && lane == 0) sm.scan.kk[t] = kt_old + 1;
            __syncthreads();
        }
        if (tid < NNODE) d_anode[tid] = ai_last;
    }
    grid_bar(3);

    // ===================== Phase 5: clip epilogue =====================
    {
        if (tid < NNODE) sm.an[tid] = d_anode[tid];
        __syncthreads();
        const int b0 = bb * 4;
        for (int i = tid; i < 4 * 512; i += NTHR) {
            int r = i >> 9, n = i & 511;
            if (n < NNODE) {
                int idx = (b0 + r) * NNODE + n;
                float q = d_qnode[idx];
                out[idx] = fminf(fmaxf(q, 0.0f), sm.an[n]);
            }
        }
    }
}

extern "C" void kernel_launch(void* const* d_in, const int* in_sizes, int n_in,
                              void* d_out, int out_size) {
    const float* x = (const float*)d_in[0];
    const float* W = (const float*)d_in[1];
    const float* b = (const float*)d_in[2];
    // d_in[3] = max_depth (fixed = 8 for this problem's shapes)
    k_fused<<<NBLK, NTHR>>>(x, W, b, (float*)d_out);
}